// round 1
// baseline (speedup 1.0000x reference)
#include <cuda_runtime.h>
#include <math.h>

// Problem constants (fixed by setup_inputs)
#define BSZ    2
#define LSEQ   4096
#define NH     16
#define HD     128
#define NSTATE 256
#define CHUNK_ 256
#define NCH    16      // LSEQ / CHUNK_
#define NBB    4       // 2*BSZ virtual batch-directions
#define DIN    2048    // NH*HD

// -------- static device scratch (no allocations allowed) --------
__device__ float g_Bt [(size_t)NBB*NCH*NSTATE*CHUNK_];   // [z][n][k]  B transposed
__device__ float g_Ct [(size_t)NBB*NCH*NSTATE*CHUNK_];   // [z][n][i]  C transposed
__device__ float g_CBT[(size_t)NBB*NCH*CHUNK_*CHUNK_];   // [z][k][i]  CB transposed
__device__ float g_states[(size_t)NBB*NCH*NH*NSTATE*HD]; // [z][h][n][p] -> prev after scan
__device__ float g_ybuf[(size_t)NBB*LSEQ*DIN];
__device__ float g_E   [(size_t)NBB*NH*LSEQ];            // exp(cs)
__device__ float g_Binv[(size_t)NBB*NH*LSEQ];            // dt * exp(-cs)
__device__ float g_Wst [(size_t)NBB*NH*LSEQ];            // dt * exp(cs_last - cs)
__device__ float g_cd  [NBB*NCH*NH];                     // exp(cs_last)

__device__ __forceinline__ size_t src_row(int bb, int t) {
    return (size_t)(bb & 1) * LSEQ + (size_t)(bb < 2 ? t : (LSEQ - 1 - t));
}

// ---------------- K1: softplus, per-chunk cumsum, exp factors ----------------
__global__ void k_pre(const float* __restrict__ dt, const float* __restrict__ A_log) {
    int c = blockIdx.x, h = blockIdx.y, bb = blockIdx.z;
    int i = threadIdx.x;
    int t = c * CHUNK_ + i;
    int trow = (bb < 2) ? t : (LSEQ - 1 - t);
    int ch   = (bb < 2) ? h : (h + NH);
    float dtv = dt[((size_t)(bb & 1) * LSEQ + trow) * (2 * NH) + ch];
    float ds  = (dtv > 20.f) ? dtv : log1pf(expf(dtv));
    float A   = -expf(A_log[h]);
    float dA  = ds * A;

    __shared__ float s[CHUNK_];
    s[i] = dA;
    __syncthreads();
    for (int off = 1; off < CHUNK_; off <<= 1) {
        float tv = (i >= off) ? s[i - off] : 0.f;
        __syncthreads();
        s[i] += tv;
        __syncthreads();
    }
    float cs = s[i];
    float cl = s[CHUNK_ - 1];
    size_t base = ((size_t)bb * NH + h) * LSEQ + t;
    g_E[base]    = expf(cs);
    g_Binv[base] = ds * expf(-cs);
    g_Wst[base]  = ds * expf(cl - cs);
    if (i == 0) g_cd[(bb * NCH + c) * NH + h] = expf(cl);
}

// ---------------- K0: transpose B and C per (dir,chunk) ----------------
__global__ void k_transpose(const float* __restrict__ BC) {
    int z = blockIdx.z;
    int c = z % NCH;
    int bb = z / NCH;
    int tBase = blockIdx.x * 32, chBase = blockIdx.y * 32;
    __shared__ float s[32][33];
    int lr = threadIdx.x >> 5;   // 0..7
    int lc = threadIdx.x & 31;
#pragma unroll
    for (int j = 0; j < 4; j++) {
        int r = lr + j * 8;
        int t = c * CHUNK_ + tBase + r;
        s[r][lc] = BC[src_row(bb, t) * (2 * NSTATE) + chBase + lc];
    }
    __syncthreads();
    float* outp = (chBase < NSTATE) ? g_Bt : g_Ct;
    int nOff = (chBase < NSTATE) ? chBase : (chBase - NSTATE);
#pragma unroll
    for (int j = 0; j < 4; j++) {
        int nl = lr + j * 8;
        outp[((size_t)z * NSTATE + nOff + nl) * CHUNK_ + tBase + lc] = s[lc][nl];
    }
}

// ---------------- K2: CBT[k][i] = sum_n B[k,n] C[i,n] ----------------
__global__ void k_cb() {
    int z = blockIdx.z;
    const float* Aop = g_Bt + (size_t)z * NSTATE * CHUNK_;  // [n][k]
    const float* Bop = g_Ct + (size_t)z * NSTATE * CHUNK_;  // [n][i]
    float* outp = g_CBT + (size_t)z * CHUNK_ * CHUNK_;
    int rowBase = blockIdx.x * 128;   // k
    int colBase = blockIdx.y * 128;   // i

    __shared__ __align__(16) float As[16][136];
    __shared__ __align__(16) float Bs[16][136];
    float acc[8][8] = {};
    int tx = threadIdx.x % 16, ty = threadIdx.x / 16;
    int lkk = threadIdx.x / 16, lcol = (threadIdx.x % 16) * 8;

    for (int n0 = 0; n0 < NSTATE; n0 += 16) {
        const float* pa = Aop + (size_t)(n0 + lkk) * CHUNK_ + rowBase + lcol;
        const float* pb = Bop + (size_t)(n0 + lkk) * CHUNK_ + colBase + lcol;
        *(float4*)&As[lkk][lcol]     = *(const float4*)pa;
        *(float4*)&As[lkk][lcol + 4] = *(const float4*)(pa + 4);
        *(float4*)&Bs[lkk][lcol]     = *(const float4*)pb;
        *(float4*)&Bs[lkk][lcol + 4] = *(const float4*)(pb + 4);
        __syncthreads();
#pragma unroll
        for (int kk = 0; kk < 16; kk++) {
            float a[8], b[8];
            *(float4*)&a[0] = *(const float4*)&As[kk][ty * 8];
            *(float4*)&a[4] = *(const float4*)&As[kk][ty * 8 + 4];
            *(float4*)&b[0] = *(const float4*)&Bs[kk][tx * 8];
            *(float4*)&b[4] = *(const float4*)&Bs[kk][tx * 8 + 4];
#pragma unroll
            for (int u = 0; u < 8; u++)
#pragma unroll
                for (int v = 0; v < 8; v++) acc[u][v] += a[u] * b[v];
        }
        __syncthreads();
    }
#pragma unroll
    for (int u = 0; u < 8; u++) {
        float* orow = outp + (size_t)(rowBase + ty * 8 + u) * CHUNK_ + colBase + tx * 8;
        *(float4*)orow       = make_float4(acc[u][0], acc[u][1], acc[u][2], acc[u][3]);
        *(float4*)(orow + 4) = make_float4(acc[u][4], acc[u][5], acc[u][6], acc[u][7]);
    }
}

// ---------------- K3: states[n][p] = sum_k (w_k B[k,n]) x[k,h,p] ----------------
__global__ void k_states(const float* __restrict__ x, const float* __restrict__ BC) {
    int z = blockIdx.z;
    int c = z % NCH;
    int bb = z / NCH;
    int h = blockIdx.y;
    int nBase = blockIdx.x * 128;

    __shared__ __align__(16) float As[16][136];
    __shared__ __align__(16) float Bs[16][136];
    float acc[8][8] = {};
    int tx = threadIdx.x % 16, ty = threadIdx.x / 16;
    int lkk = threadIdx.x / 16, lcol = (threadIdx.x % 16) * 8;

    for (int k0 = 0; k0 < CHUNK_; k0 += 16) {
        int t = c * CHUNK_ + k0 + lkk;
        size_t r = src_row(bb, t);
        float w = g_Wst[((size_t)bb * NH + h) * LSEQ + t];
        const float* brow = BC + r * (2 * NSTATE) + nBase + lcol;
        float4 a0 = *(const float4*)brow;
        float4 a1 = *(const float4*)(brow + 4);
        a0.x *= w; a0.y *= w; a0.z *= w; a0.w *= w;
        a1.x *= w; a1.y *= w; a1.z *= w; a1.w *= w;
        *(float4*)&As[lkk][lcol]     = a0;
        *(float4*)&As[lkk][lcol + 4] = a1;
        const float* xrow = x + r * DIN + h * HD + lcol;
        *(float4*)&Bs[lkk][lcol]     = *(const float4*)xrow;
        *(float4*)&Bs[lkk][lcol + 4] = *(const float4*)(xrow + 4);
        __syncthreads();
#pragma unroll
        for (int kk = 0; kk < 16; kk++) {
            float a[8], b[8];
            *(float4*)&a[0] = *(const float4*)&As[kk][ty * 8];
            *(float4*)&a[4] = *(const float4*)&As[kk][ty * 8 + 4];
            *(float4*)&b[0] = *(const float4*)&Bs[kk][tx * 8];
            *(float4*)&b[4] = *(const float4*)&Bs[kk][tx * 8 + 4];
#pragma unroll
            for (int u = 0; u < 8; u++)
#pragma unroll
                for (int v = 0; v < 8; v++) acc[u][v] += a[u] * b[v];
        }
        __syncthreads();
    }
    size_t sb = ((size_t)z * NH + h) * NSTATE * HD;
#pragma unroll
    for (int u = 0; u < 8; u++) {
        float* orow = g_states + sb + (size_t)(nBase + ty * 8 + u) * HD + tx * 8;
        *(float4*)orow       = make_float4(acc[u][0], acc[u][1], acc[u][2], acc[u][3]);
        *(float4*)(orow + 4) = make_float4(acc[u][4], acc[u][5], acc[u][6], acc[u][7]);
    }
}

// ---------------- K4: inter-chunk scan (in place: states -> prev) ----------------
__global__ void k_scan() {
    int idx = blockIdx.x * blockDim.x + threadIdx.x;
    int p = idx & (HD - 1);
    int n = (idx / HD) & (NSTATE - 1);
    int h = (idx / (HD * NSTATE)) & (NH - 1);
    int bb = idx / (HD * NSTATE * NH);
    size_t rest = ((size_t)h * NSTATE + n) * HD + p;
    size_t stride = (size_t)NH * NSTATE * HD;
    float carry = 0.f;
    for (int c = 0; c < NCH; c++) {
        size_t off = (size_t)(bb * NCH + c) * stride + rest;
        float sv = g_states[off];
        g_states[off] = carry;
        carry = carry * g_cd[(bb * NCH + c) * NH + h] + sv;
    }
}

// ---------------- K5: y = e_i * ( (CBT*binv*mask) @ X + C @ prev ) ----------------
__global__ void k_y(const float* __restrict__ x) {
    int z = blockIdx.z;
    int c = z % NCH;
    int bb = z / NCH;
    int h = blockIdx.y;
    int iBase = blockIdx.x * 128;

    __shared__ __align__(16) float As[16][136];
    __shared__ __align__(16) float Bs[16][136];
    float acc[8][8] = {};
    int tx = threadIdx.x % 16, ty = threadIdx.x / 16;
    int lkk = threadIdx.x / 16, lcol = (threadIdx.x % 16) * 8;

    // phase 1: intra-chunk, reduce over k
    const float* CBT = g_CBT + (size_t)z * CHUNK_ * CHUNK_;
    for (int k0 = 0; k0 < CHUNK_; k0 += 16) {
        int kg = k0 + lkk;
        int t = c * CHUNK_ + kg;
        float binv = g_Binv[((size_t)bb * NH + h) * LSEQ + t];
        const float* crow = CBT + (size_t)kg * CHUNK_ + iBase + lcol;
        float4 a0 = *(const float4*)crow;
        float4 a1 = *(const float4*)(crow + 4);
        int ig = iBase + lcol;
        a0.x = (kg <= ig + 0) ? a0.x * binv : 0.f;
        a0.y = (kg <= ig + 1) ? a0.y * binv : 0.f;
        a0.z = (kg <= ig + 2) ? a0.z * binv : 0.f;
        a0.w = (kg <= ig + 3) ? a0.w * binv : 0.f;
        a1.x = (kg <= ig + 4) ? a1.x * binv : 0.f;
        a1.y = (kg <= ig + 5) ? a1.y * binv : 0.f;
        a1.z = (kg <= ig + 6) ? a1.z * binv : 0.f;
        a1.w = (kg <= ig + 7) ? a1.w * binv : 0.f;
        *(float4*)&As[lkk][lcol]     = a0;
        *(float4*)&As[lkk][lcol + 4] = a1;
        size_t r = src_row(bb, t);
        const float* xrow = x + r * DIN + h * HD + lcol;
        *(float4*)&Bs[lkk][lcol]     = *(const float4*)xrow;
        *(float4*)&Bs[lkk][lcol + 4] = *(const float4*)(xrow + 4);
        __syncthreads();
#pragma unroll
        for (int kk = 0; kk < 16; kk++) {
            float a[8], b[8];
            *(float4*)&a[0] = *(const float4*)&As[kk][ty * 8];
            *(float4*)&a[4] = *(const float4*)&As[kk][ty * 8 + 4];
            *(float4*)&b[0] = *(const float4*)&Bs[kk][tx * 8];
            *(float4*)&b[4] = *(const float4*)&Bs[kk][tx * 8 + 4];
#pragma unroll
            for (int u = 0; u < 8; u++)
#pragma unroll
                for (int v = 0; v < 8; v++) acc[u][v] += a[u] * b[v];
        }
        __syncthreads();
    }

    // phase 2: inter-chunk, reduce over n
    const float* Ct = g_Ct + (size_t)z * NSTATE * CHUNK_;
    const float* prev = g_states + ((size_t)z * NH + h) * NSTATE * HD;
    for (int n0 = 0; n0 < NSTATE; n0 += 16) {
        const float* crow = Ct + (size_t)(n0 + lkk) * CHUNK_ + iBase + lcol;
        *(float4*)&As[lkk][lcol]     = *(const float4*)crow;
        *(float4*)&As[lkk][lcol + 4] = *(const float4*)(crow + 4);
        const float* prow = prev + (size_t)(n0 + lkk) * HD + lcol;
        *(float4*)&Bs[lkk][lcol]     = *(const float4*)prow;
        *(float4*)&Bs[lkk][lcol + 4] = *(const float4*)(prow + 4);
        __syncthreads();
#pragma unroll
        for (int kk = 0; kk < 16; kk++) {
            float a[8], b[8];
            *(float4*)&a[0] = *(const float4*)&As[kk][ty * 8];
            *(float4*)&a[4] = *(const float4*)&As[kk][ty * 8 + 4];
            *(float4*)&b[0] = *(const float4*)&Bs[kk][tx * 8];
            *(float4*)&b[4] = *(const float4*)&Bs[kk][tx * 8 + 4];
#pragma unroll
            for (int u = 0; u < 8; u++)
#pragma unroll
                for (int v = 0; v < 8; v++) acc[u][v] += a[u] * b[v];
        }
        __syncthreads();
    }

    // epilogue: scale rows by exp(cs_i), write y
#pragma unroll
    for (int u = 0; u < 8; u++) {
        int ig = iBase + ty * 8 + u;
        int t = c * CHUNK_ + ig;
        float e = g_E[((size_t)bb * NH + h) * LSEQ + t];
        float* yr = g_ybuf + ((size_t)bb * LSEQ + t) * DIN + h * HD + tx * 8;
        *(float4*)yr       = make_float4(acc[u][0] * e, acc[u][1] * e, acc[u][2] * e, acc[u][3] * e);
        *(float4*)(yr + 4) = make_float4(acc[u][4] * e, acc[u][5] * e, acc[u][6] * e, acc[u][7] * e);
    }
}

// ---------------- K6: gate GEMV + roll/flip combine ----------------
__global__ void k_final(const float* __restrict__ x, const float* __restrict__ W,
                        const float* __restrict__ Dp, float* __restrict__ out) {
    int t = blockIdx.x;
    int b = blockIdx.y;
    __shared__ float xs[DIN];
    __shared__ float gate[NH];
    const float* xrow = x + ((size_t)b * LSEQ + t) * DIN;
    for (int d = threadIdx.x; d < DIN; d += 256) xs[d] = xrow[d];
    __syncthreads();
    int warp = threadIdx.x / 32, lane = threadIdx.x % 32;
#pragma unroll
    for (int hh = 0; hh < 2; hh++) {
        int h = warp * 2 + hh;
        const float* wrow = W + (size_t)h * DIN;
        float acc = 0.f;
        for (int d = lane; d < DIN; d += 32) acc += xs[d] * wrow[d];
#pragma unroll
        for (int o = 16; o; o >>= 1) acc += __shfl_down_sync(0xFFFFFFFFu, acc, o);
        if (lane == 0) gate[h] = acc + Dp[h];
    }
    __syncthreads();
    const float* yf = (t == 0) ? nullptr : (g_ybuf + ((size_t)b * LSEQ + (t - 1)) * DIN);
    int tb = LSEQ - 1 - t;
    const float* yb = (tb == 0) ? nullptr : (g_ybuf + ((size_t)(b + 2) * LSEQ + (tb - 1)) * DIN);
    float* orow = out + ((size_t)b * LSEQ + t) * DIN;
    for (int d = threadIdx.x; d < DIN; d += 256) {
        float v = xs[d] * gate[d >> 7];
        if (yf) v += yf[d];
        if (yb) v += yb[d];
        orow[d] = v;
    }
}

// ---------------- launch ----------------
extern "C" void kernel_launch(void* const* d_in, const int* in_sizes, int n_in,
                              void* d_out, int out_size) {
    const float* x     = (const float*)d_in[0];
    const float* BC    = (const float*)d_in[1];
    const float* dt    = (const float*)d_in[2];
    const float* A_log = (const float*)d_in[3];
    const float* Dv    = (const float*)d_in[4];
    const float* W     = (const float*)d_in[5];
    float* out = (float*)d_out;

    k_pre      <<<dim3(NCH, NH, NBB), 256>>>(dt, A_log);
    k_transpose<<<dim3(8, 16, NBB * NCH), 256>>>(BC);
    k_cb       <<<dim3(2, 2, NBB * NCH), 256>>>();
    k_states   <<<dim3(2, NH, NBB * NCH), 256>>>(x, BC);
    k_scan     <<<(NBB * NH * NSTATE * HD) / 256, 256>>>();
    k_y        <<<dim3(2, NH, NBB * NCH), 256>>>(x);
    k_final    <<<dim3(LSEQ, BSZ), 256>>>(x, W, Dv, out);
}